// round 2
// baseline (speedup 1.0000x reference)
#include <cuda_runtime.h>
#include <math.h>

#define NI 128
#define NT 128
#define RR 48
#define LW 64
#define DD 1024
#define MM (NI*RR)   /* 6144 */
#define NN (NT*LW)   /* 8192 */
#define EPSV 1e-8f
#define LAM 20.0f

// ---------------- scratch (static device globals; no allocation) ----------------
__device__ float g_qn[MM*DD];                 // 25 MB  normalized img_q
__device__ float g_tkn[NN*DD];                // 34 MB  masked-normalized txt_k
__device__ float g_S[50331648];               // 201 MB S = qn . tkn^T   [6144 x 8192]
__device__ float g_C[50331648];               // 201 MB C = img_v . txt_v^T
__device__ float g_G[NT*LW*LW];               // 2 MB   per-text Gram of txt_v
__device__ float g_H[NI*RR*RR];               // 1.2 MB per-image Gram of img_v
__device__ float g_niv[MM];                   // |img_v[n,r]|
__device__ float g_ntv[NN];                   // |txt_v[t,l]|

// ---------------- warp helpers ----------------
__device__ __forceinline__ float wsum(float v){
#pragma unroll
    for (int o = 16; o; o >>= 1) v += __shfl_xor_sync(0xffffffffu, v, o);
    return v;
}
__device__ __forceinline__ float wmax(float v){
#pragma unroll
    for (int o = 16; o; o >>= 1) v = fmaxf(v, __shfl_xor_sync(0xffffffffu, v, o));
    return v;
}

// ---------------- prep: normalize img_q rows, norms of img_v rows ----------------
__global__ void prep_img_kernel(const float* __restrict__ q, const float* __restrict__ v){
    int row = blockIdx.x, tid = threadIdx.x;
    const float4* q4 = (const float4*)(q + (size_t)row * DD);
    const float4* v4 = (const float4*)(v + (size_t)row * DD);
    float4 a = q4[tid], b = v4[tid];
    float sq = a.x*a.x + a.y*a.y + a.z*a.z + a.w*a.w;
    float sv = b.x*b.x + b.y*b.y + b.z*b.z + b.w*b.w;
    __shared__ float s1[8], s2[8];
    sq = wsum(sq); sv = wsum(sv);
    int w = tid >> 5, ln = tid & 31;
    if (ln == 0){ s1[w] = sq; s2[w] = sv; }
    __syncthreads();
    if (tid == 0){
        float t1 = 0.f, t2 = 0.f;
        for (int i = 0; i < 8; i++){ t1 += s1[i]; t2 += s2[i]; }
        s1[0] = t1;
        g_niv[row] = sqrtf(t2);
    }
    __syncthreads();
    float inv = 1.0f / (sqrtf(s1[0]) + EPSV);
    float4 o; o.x = a.x*inv; o.y = a.y*inv; o.z = a.z*inv; o.w = a.w*inv;
    ((float4*)(g_qn + (size_t)row * DD))[tid] = o;
}

// ---------------- prep: masked-normalize txt_k rows, norms of txt_v rows ----------------
__global__ void prep_txt_kernel(const float* __restrict__ k, const float* __restrict__ v,
                                const int* __restrict__ tlen){
    int row = blockIdx.x, tid = threadIdx.x;
    int t = row >> 6, l = row & 63;
    int len = tlen[t];
    const float4* k4 = (const float4*)(k + (size_t)row * DD);
    const float4* v4 = (const float4*)(v + (size_t)row * DD);
    float4 a = k4[tid], b = v4[tid];
    float sk = a.x*a.x + a.y*a.y + a.z*a.z + a.w*a.w;
    float sv = b.x*b.x + b.y*b.y + b.z*b.z + b.w*b.w;
    __shared__ float s1[8], s2[8];
    sk = wsum(sk); sv = wsum(sv);
    int w = tid >> 5, ln = tid & 31;
    if (ln == 0){ s1[w] = sk; s2[w] = sv; }
    __syncthreads();
    if (tid == 0){
        float t1 = 0.f, t2 = 0.f;
        for (int i = 0; i < 8; i++){ t1 += s1[i]; t2 += s2[i]; }
        s1[0] = t1;
        g_ntv[row] = sqrtf(t2);
    }
    __syncthreads();
    float inv = (l < len) ? (1.0f / (sqrtf(s1[0]) + EPSV)) : 0.0f;
    float4 o; o.x = a.x*inv; o.y = a.y*inv; o.z = a.z*inv; o.w = a.w*inv;
    ((float4*)(g_tkn + (size_t)row * DD))[tid] = o;
}

// ---------------- per-batch Gram: out[b] = X[b] X[b]^T, X[b] is [Rn,1024] ----------------
template<int Rn>
__global__ void gram_kernel(const float* __restrict__ X, float* __restrict__ out){
    __shared__ float sX[64][65];
    int b = blockIdx.x, tid = threadIdx.x;
    int tx = tid & 15, ty = tid >> 4;
    const float* Xb = X + (size_t)b * Rn * DD;
    int i0 = ty * 4, j0 = tx * 4;
    bool act = (i0 < Rn) && (j0 < Rn);
    float acc[4][4];
#pragma unroll
    for (int i = 0; i < 4; i++)
#pragma unroll
        for (int j = 0; j < 4; j++) acc[i][j] = 0.f;
    const int nld = Rn * 16;  // float4 per 64-wide chunk
    for (int kc = 0; kc < DD; kc += 64){
        for (int idx = tid; idx < nld; idx += 256){
            int r = idx >> 4, kq = idx & 15;
            float4 val = *(const float4*)(Xb + (size_t)r * DD + kc + kq * 4);
            sX[r][kq*4+0] = val.x; sX[r][kq*4+1] = val.y;
            sX[r][kq*4+2] = val.z; sX[r][kq*4+3] = val.w;
        }
        __syncthreads();
        if (act){
#pragma unroll 8
            for (int k = 0; k < 64; k++){
                float ai0 = sX[i0+0][k], ai1 = sX[i0+1][k], ai2 = sX[i0+2][k], ai3 = sX[i0+3][k];
                float bj0 = sX[j0+0][k], bj1 = sX[j0+1][k], bj2 = sX[j0+2][k], bj3 = sX[j0+3][k];
                acc[0][0] += ai0*bj0; acc[0][1] += ai0*bj1; acc[0][2] += ai0*bj2; acc[0][3] += ai0*bj3;
                acc[1][0] += ai1*bj0; acc[1][1] += ai1*bj1; acc[1][2] += ai1*bj2; acc[1][3] += ai1*bj3;
                acc[2][0] += ai2*bj0; acc[2][1] += ai2*bj1; acc[2][2] += ai2*bj2; acc[2][3] += ai2*bj3;
                acc[3][0] += ai3*bj0; acc[3][1] += ai3*bj1; acc[3][2] += ai3*bj2; acc[3][3] += ai3*bj3;
            }
        }
        __syncthreads();
    }
    if (act){
        float* ob = out + (size_t)b * Rn * Rn;
#pragma unroll
        for (int a = 0; a < 4; a++)
#pragma unroll
            for (int c = 0; c < 4; c++)
                ob[(i0+a)*Rn + j0 + c] = acc[a][c];
    }
}

// ---------------- SGEMM: Cg[M,NN] = A[M,1024] * B[NN,1024]^T (128x128x16 tiles) ----------------
__global__ void sgemm_nt(const float* __restrict__ A, const float* __restrict__ B,
                         float* __restrict__ Cg){
    __shared__ float As[16][132];
    __shared__ float Bs[16][132];
    int tid = threadIdx.x, tx = tid & 15, ty = tid >> 4;
    const float* Ab = A + (size_t)blockIdx.y * 128 * DD;
    const float* Bb = B + (size_t)blockIdx.x * 128 * DD;
    float acc[8][8];
#pragma unroll
    for (int i = 0; i < 8; i++)
#pragma unroll
        for (int j = 0; j < 8; j++) acc[i][j] = 0.f;

    for (int kt = 0; kt < DD; kt += 16){
#pragma unroll
        for (int u = 0; u < 2; u++){
            int idx = tid * 2 + u;
            int r = idx >> 2, kq = idx & 3;
            float4 av = *(const float4*)(Ab + (size_t)r * DD + kt + kq * 4);
            As[kq*4+0][r] = av.x; As[kq*4+1][r] = av.y;
            As[kq*4+2][r] = av.z; As[kq*4+3][r] = av.w;
            float4 bv = *(const float4*)(Bb + (size_t)r * DD + kt + kq * 4);
            Bs[kq*4+0][r] = bv.x; Bs[kq*4+1][r] = bv.y;
            Bs[kq*4+2][r] = bv.z; Bs[kq*4+3][r] = bv.w;
        }
        __syncthreads();
#pragma unroll
        for (int k = 0; k < 16; k++){
            float4 a0 = *(const float4*)&As[k][ty*4];
            float4 a1 = *(const float4*)&As[k][64 + ty*4];
            float4 b0 = *(const float4*)&Bs[k][tx*4];
            float4 b1 = *(const float4*)&Bs[k][64 + tx*4];
            float am[8] = {a0.x,a0.y,a0.z,a0.w,a1.x,a1.y,a1.z,a1.w};
            float bn[8] = {b0.x,b0.y,b0.z,b0.w,b1.x,b1.y,b1.z,b1.w};
#pragma unroll
            for (int i = 0; i < 8; i++)
#pragma unroll
                for (int j = 0; j < 8; j++)
                    acc[i][j] += am[i] * bn[j];
        }
        __syncthreads();
    }
    size_t colb = (size_t)blockIdx.x * 128;
#pragma unroll
    for (int gi = 0; gi < 2; gi++)
#pragma unroll
        for (int a = 0; a < 4; a++){
            int m = blockIdx.y * 128 + gi * 64 + ty * 4 + a;
            float* cp = Cg + (size_t)m * NN + colb;
            float4 o0 = {acc[gi*4+a][0], acc[gi*4+a][1], acc[gi*4+a][2], acc[gi*4+a][3]};
            float4 o1 = {acc[gi*4+a][4], acc[gi*4+a][5], acc[gi*4+a][6], acc[gi*4+a][7]};
            *(float4*)(cp + tx*4) = o0;
            *(float4*)(cp + 64 + tx*4) = o1;
        }
}

// ---------------- epilogue: per (n,t) pair attention + focal + cosine ----------------
__global__ void epilogue_kernel(const int* __restrict__ tlen, float* __restrict__ out){
    __shared__ float sS[RR*65];    // leaky(S) tile  [48][65]
    __shared__ float sCt[LW*49];   // C tile transposed [64][49]: sCt[l*49+r]
    __shared__ float sGH[LW*65];   // G tile [64][65], later H tile [48][49]
    __shared__ float colnorm[LW];
    __shared__ float rownorm[RR];
    __shared__ float wacc[8];

    int n = blockIdx.y, t = blockIdx.x;
    int tid = threadIdx.x, warp = tid >> 5, lane = tid & 31;
    int len = tlen[t];
    float lenf = (float)len;

    // loads: S (with leaky), C (transposed), G
    for (int idx = tid; idx < RR*16; idx += 256){
        int r = idx >> 4, q = idx & 15;
        float4 v = *(const float4*)(g_S + (size_t)(n*RR + r) * NN + t*LW + q*4);
        float* d = &sS[r*65 + q*4];
        d[0] = v.x >= 0.f ? v.x : 0.1f*v.x;
        d[1] = v.y >= 0.f ? v.y : 0.1f*v.y;
        d[2] = v.z >= 0.f ? v.z : 0.1f*v.z;
        d[3] = v.w >= 0.f ? v.w : 0.1f*v.w;
    }
    for (int idx = tid; idx < RR*16; idx += 256){
        int r = idx >> 4, q = idx & 15;
        float4 v = *(const float4*)(g_C + (size_t)(n*RR + r) * NN + t*LW + q*4);
        sCt[(q*4+0)*49 + r] = v.x; sCt[(q*4+1)*49 + r] = v.y;
        sCt[(q*4+2)*49 + r] = v.z; sCt[(q*4+3)*49 + r] = v.w;
    }
    for (int idx = tid; idx < LW*16; idx += 256){
        int l = idx >> 4, q = idx & 15;
        float4 v = *(const float4*)(g_G + (size_t)t*LW*LW + l*LW + q*4);
        float* d = &sGH[l*65 + q*4];
        d[0] = v.x; d[1] = v.y; d[2] = v.z; d[3] = v.w;
    }
    __syncthreads();

    if (tid < LW){
        float s = 0.f;
        for (int r = 0; r < RR; r++){ float v = sS[r*65 + tid]; s += v*v; }
        colnorm[tid] = sqrtf(s) + EPSV;
    } else if (tid < LW + RR){
        int r = tid - LW; float s = 0.f;
        for (int l = 0; l < LW; l++){ float v = sS[r*65 + l]; s += v*v; }
        rownorm[r] = sqrtf(s) + EPSV;
    }
    __syncthreads();

    // ---- i2t: softmax over words (masked), focal, cosine vs img_v ----
    float accI = 0.f;
    for (int r = warp; r < RR; r += 8){
        int l0 = lane, l1 = lane + 32;
        bool m0 = l0 < len, m1 = l1 < len;
        float x0 = m0 ? sS[r*65 + l0] / colnorm[l0] * LAM : -1e30f;
        float x1 = m1 ? sS[r*65 + l1] / colnorm[l1] * LAM : -1e30f;
        float mx = wmax(fmaxf(x0, x1));
        float e0 = m0 ? expf(x0 - mx) : 0.f;
        float e1 = m1 ? expf(x1 - mx) : 0.f;
        float sE = wsum(e0 + e1);
        float a0 = e0 / sE, a1 = e1 / sE;
        float sA = wsum(a0 + a1);
        float ta0 = (a0 * lenf - sA > 0.f) ? a0 : 0.f;
        float ta1 = (a1 * lenf - sA > 0.f) ? a1 : 0.f;
        float sT = wsum(ta0 + ta1);
        float dn = sT > 0.f ? sT : 1.f;
        float f0 = ta0 / dn, f1 = ta1 / dn;
        float num = wsum(f0 * sCt[l0*49 + r] + f1 * sCt[l1*49 + r]);
        float qd = 0.f;
        for (int lp = 0; lp < LW; lp++){
            float alp = (lp < 32) ? __shfl_sync(0xffffffffu, f0, lp)
                                  : __shfl_sync(0xffffffffu, f1, lp - 32);
            qd += alp * (f0 * sGH[l0*65 + lp] + f1 * sGH[l1*65 + lp]);
        }
        qd = wsum(qd);
        float wn = sqrtf(fmaxf(qd, 0.f));
        float inv = 1.f / (wn + EPSV);
        float xw = num * inv, whn = wn * inv;
        float den = fmaxf(g_niv[n*RR + r] * whn, EPSV);
        accI += xw / den;
    }
    if (lane == 0) wacc[warp] = accI;
    __syncthreads();
    if (tid == 0){
        float s = 0.f;
        for (int i = 0; i < 8; i++) s += wacc[i];
        out[n*NT + t] = s / (float)RR;
    }
    __syncthreads();

    // overwrite sGH with H[n]
    for (int idx = tid; idx < RR*RR; idx += 256){
        int r = idx / RR, c = idx - r*RR;
        sGH[r*49 + c] = g_H[(size_t)n*RR*RR + idx];
    }
    __syncthreads();

    // ---- t2i: softmax over regions, focal, cosine vs txt_v ----
    float accT = 0.f;
    for (int l = warp; l < LW; l += 8){
        int r0 = lane;
        bool h1 = lane < 16;
        int r1 = lane + 32;
        float y0 = sS[r0*65 + l] / rownorm[r0] * LAM;
        float y1 = h1 ? sS[r1*65 + l] / rownorm[r1] * LAM : -1e30f;
        float mx = wmax(fmaxf(y0, y1));
        float e0 = expf(y0 - mx);
        float e1 = h1 ? expf(y1 - mx) : 0.f;
        float sE = wsum(e0 + e1);
        float a0 = e0 / sE, a1 = e1 / sE;
        float sA = wsum(a0 + a1);
        float ta0 = (a0 * (float)RR - sA > 0.f) ? a0 : 0.f;
        float ta1 = (a1 * (float)RR - sA > 0.f) ? a1 : 0.f;
        float sT = wsum(ta0 + ta1);
        float dn = sT > 0.f ? sT : 1.f;
        float f0 = ta0 / dn, f1 = ta1 / dn;
        float num = f0 * sCt[l*49 + r0] + (h1 ? f1 * sCt[l*49 + r1] : 0.f);
        num = wsum(num);
        float qd = 0.f;
        for (int rp = 0; rp < RR; rp++){
            float arp = (rp < 32) ? __shfl_sync(0xffffffffu, f0, rp)
                                  : __shfl_sync(0xffffffffu, f1, rp - 32);
            float term = f0 * sGH[r0*49 + rp];
            if (h1) term += f1 * sGH[r1*49 + rp];
            qd += arp * term;
        }
        qd = wsum(qd);
        float wn = sqrtf(fmaxf(qd, 0.f));
        float inv = 1.f / (wn + EPSV);
        float xw = num * inv, whn = wn * inv;
        float den = fmaxf(g_ntv[t*LW + l] * whn, EPSV);
        float c2 = xw / den;
        if (l < len) accT += c2;
    }
    if (lane == 0) wacc[warp] = accT;
    __syncthreads();
    if (tid == 0){
        float s = 0.f;
        for (int i = 0; i < 8; i++) s += wacc[i];
        out[NI*NT + n*NT + t] = s / lenf;
    }
}

// ---------------- launch ----------------
extern "C" void kernel_launch(void* const* d_in, const int* in_sizes, int n_in,
                              void* d_out, int out_size){
    (void)in_sizes; (void)n_in; (void)out_size;
    const float* img_q = (const float*)d_in[0];
    const float* img_v = (const float*)d_in[1];
    const float* txt_k = (const float*)d_in[2];
    const float* txt_v = (const float*)d_in[3];
    const int*   tlen  = (const int*)d_in[4];
    float* out = (float*)d_out;

    void *pqn, *ptkn, *pS, *pC, *pG, *pH;
    cudaGetSymbolAddress(&pqn, g_qn);
    cudaGetSymbolAddress(&ptkn, g_tkn);
    cudaGetSymbolAddress(&pS, g_S);
    cudaGetSymbolAddress(&pC, g_C);
    cudaGetSymbolAddress(&pG, g_G);
    cudaGetSymbolAddress(&pH, g_H);

    prep_img_kernel<<<MM, 256>>>(img_q, img_v);
    prep_txt_kernel<<<NN, 256>>>(txt_k, txt_v, tlen);
    gram_kernel<RR><<<NI, 256>>>(img_v, (float*)pH);
    gram_kernel<LW><<<NT, 256>>>(txt_v, (float*)pG);

    dim3 gg(NN/128, MM/128);   // 64 x 48
    sgemm_nt<<<gg, 256>>>((const float*)pqn, (const float*)ptkn, (float*)pS);
    sgemm_nt<<<gg, 256>>>(img_v, txt_v, (float*)pC);

    dim3 ge(NT, NI);           // x = t, y = n
    epilogue_kernel<<<ge, 256>>>(tlen, out);
}

// round 5
// speedup vs baseline: 1.2721x; 1.2721x over previous
#include <cuda_runtime.h>
#include <math.h>

#define NI 128
#define NT 128
#define RR 48
#define LW 64
#define DD 1024
#define MM (NI*RR)   /* 6144 */
#define NN (NT*LW)   /* 8192 */
#define EPSV 1e-8f
#define LAM 20.0f

// ---------------- scratch (static device globals; no allocation) ----------------
__device__ float g_qn[MM*DD];                 // 25 MB  normalized img_q
__device__ float g_tkn[NN*DD];                // 34 MB  masked-normalized txt_k
__device__ float g_S[50331648];               // 201 MB S = qn . tkn^T   [6144 x 8192]
__device__ float g_C[50331648];               // 201 MB C = img_v . txt_v^T
__device__ float g_G[NT*LW*LW];               // 2 MB   per-text Gram of txt_v
__device__ float g_H[NI*RR*RR];               // 1.2 MB per-image Gram of img_v
__device__ float g_niv[MM];                   // |img_v[n,r]|
__device__ float g_ntv[NN];                   // |txt_v[t,l]|

// ---------------- warp helpers ----------------
__device__ __forceinline__ float wsum(float v){
#pragma unroll
    for (int o = 16; o; o >>= 1) v += __shfl_xor_sync(0xffffffffu, v, o);
    return v;
}
__device__ __forceinline__ float wmax(float v){
#pragma unroll
    for (int o = 16; o; o >>= 1) v = fmaxf(v, __shfl_xor_sync(0xffffffffu, v, o));
    return v;
}

// ---------------- prep: normalize img_q rows, norms of img_v rows ----------------
__global__ void prep_img_kernel(const float* __restrict__ q, const float* __restrict__ v){
    int row = blockIdx.x, tid = threadIdx.x;
    const float4* q4 = (const float4*)(q + (size_t)row * DD);
    const float4* v4 = (const float4*)(v + (size_t)row * DD);
    float4 a = q4[tid], b = v4[tid];
    float sq = a.x*a.x + a.y*a.y + a.z*a.z + a.w*a.w;
    float sv = b.x*b.x + b.y*b.y + b.z*b.z + b.w*b.w;
    __shared__ float s1[8], s2[8];
    sq = wsum(sq); sv = wsum(sv);
    int w = tid >> 5, ln = tid & 31;
    if (ln == 0){ s1[w] = sq; s2[w] = sv; }
    __syncthreads();
    if (tid == 0){
        float t1 = 0.f, t2 = 0.f;
        for (int i = 0; i < 8; i++){ t1 += s1[i]; t2 += s2[i]; }
        s1[0] = t1;
        g_niv[row] = sqrtf(t2);
    }
    __syncthreads();
    float inv = 1.0f / (sqrtf(s1[0]) + EPSV);
    float4 o; o.x = a.x*inv; o.y = a.y*inv; o.z = a.z*inv; o.w = a.w*inv;
    ((float4*)(g_qn + (size_t)row * DD))[tid] = o;
}

// ---------------- prep: masked-normalize txt_k rows, norms of txt_v rows ----------------
__global__ void prep_txt_kernel(const float* __restrict__ k, const float* __restrict__ v,
                                const int* __restrict__ tlen){
    int row = blockIdx.x, tid = threadIdx.x;
    int t = row >> 6, l = row & 63;
    int len = tlen[t];
    const float4* k4 = (const float4*)(k + (size_t)row * DD);
    const float4* v4 = (const float4*)(v + (size_t)row * DD);
    float4 a = k4[tid], b = v4[tid];
    float sk = a.x*a.x + a.y*a.y + a.z*a.z + a.w*a.w;
    float sv = b.x*b.x + b.y*b.y + b.z*b.z + b.w*b.w;
    __shared__ float s1[8], s2[8];
    sk = wsum(sk); sv = wsum(sv);
    int w = tid >> 5, ln = tid & 31;
    if (ln == 0){ s1[w] = sk; s2[w] = sv; }
    __syncthreads();
    if (tid == 0){
        float t1 = 0.f, t2 = 0.f;
        for (int i = 0; i < 8; i++){ t1 += s1[i]; t2 += s2[i]; }
        s1[0] = t1;
        g_ntv[row] = sqrtf(t2);
    }
    __syncthreads();
    float inv = (l < len) ? (1.0f / (sqrtf(s1[0]) + EPSV)) : 0.0f;
    float4 o; o.x = a.x*inv; o.y = a.y*inv; o.z = a.z*inv; o.w = a.w*inv;
    ((float4*)(g_tkn + (size_t)row * DD))[tid] = o;
}

// ---------------- per-batch Gram: out[b] = X[b] X[b]^T, X[b] is [Rn,1024] ----------------
template<int Rn>
__global__ void gram_kernel(const float* __restrict__ X, float* __restrict__ out){
    __shared__ float sX[64][65];
    int b = blockIdx.x, tid = threadIdx.x;
    int tx = tid & 15, ty = tid >> 4;
    const float* Xb = X + (size_t)b * Rn * DD;
    int i0 = ty * 4, j0 = tx * 4;
    bool act = (i0 < Rn) && (j0 < Rn);
    float acc[4][4];
#pragma unroll
    for (int i = 0; i < 4; i++)
#pragma unroll
        for (int j = 0; j < 4; j++) acc[i][j] = 0.f;
    const int nld = Rn * 16;  // float4 per 64-wide chunk
    for (int kc = 0; kc < DD; kc += 64){
        for (int idx = tid; idx < nld; idx += 256){
            int r = idx >> 4, kq = idx & 15;
            float4 val = *(const float4*)(Xb + (size_t)r * DD + kc + kq * 4);
            sX[r][kq*4+0] = val.x; sX[r][kq*4+1] = val.y;
            sX[r][kq*4+2] = val.z; sX[r][kq*4+3] = val.w;
        }
        __syncthreads();
        if (act){
#pragma unroll 8
            for (int k = 0; k < 64; k++){
                float ai0 = sX[i0+0][k], ai1 = sX[i0+1][k], ai2 = sX[i0+2][k], ai3 = sX[i0+3][k];
                float bj0 = sX[j0+0][k], bj1 = sX[j0+1][k], bj2 = sX[j0+2][k], bj3 = sX[j0+3][k];
                acc[0][0] += ai0*bj0; acc[0][1] += ai0*bj1; acc[0][2] += ai0*bj2; acc[0][3] += ai0*bj3;
                acc[1][0] += ai1*bj0; acc[1][1] += ai1*bj1; acc[1][2] += ai1*bj2; acc[1][3] += ai1*bj3;
                acc[2][0] += ai2*bj0; acc[2][1] += ai2*bj1; acc[2][2] += ai2*bj2; acc[2][3] += ai2*bj3;
                acc[3][0] += ai3*bj0; acc[3][1] += ai3*bj1; acc[3][2] += ai3*bj2; acc[3][3] += ai3*bj3;
            }
        }
        __syncthreads();
    }
    if (act){
        float* ob = out + (size_t)b * Rn * Rn;
#pragma unroll
        for (int a = 0; a < 4; a++)
#pragma unroll
            for (int c = 0; c < 4; c++)
                ob[(i0+a)*Rn + j0 + c] = acc[a][c];
    }
}

// ---------------- 3xTF32 tensor-core SGEMM: Cg[M,NN] = A[M,1024] * B[NN,1024]^T --------
// CTA tile 128x128, K-chunk 32, 8 warps each computing 32x64.
// smem holds hi/lo tf32 split: error ~2^-22 (fp32-equivalent).

#define KP 36   /* padded k-stride in floats: conflict-free frags, 16B aligned */

__device__ __forceinline__ void tf32_split(float v, float& hi, float& lo){
    unsigned h;
    asm("cvt.rna.tf32.f32 %0, %1;" : "=r"(h) : "f"(v));
    hi = __uint_as_float(h);
    float l = v - hi;
    unsigned l2;
    asm("cvt.rna.tf32.f32 %0, %1;" : "=r"(l2) : "f"(l));
    lo = __uint_as_float(l2);
}

#define MMA_TF32(d, a0,a1,a2,a3, b0,b1) \
    asm volatile("mma.sync.aligned.m16n8k8.row.col.f32.tf32.tf32.f32 " \
        "{%0,%1,%2,%3}, {%4,%5,%6,%7}, {%8,%9}, {%0,%1,%2,%3};" \
        : "+f"(d[0]), "+f"(d[1]), "+f"(d[2]), "+f"(d[3]) \
        : "r"(a0), "r"(a1), "r"(a2), "r"(a3), "r"(b0), "r"(b1))

__global__ __launch_bounds__(256, 1)
void sgemm_tf32x3(const float* __restrict__ A, const float* __restrict__ B,
                  float* __restrict__ Cg){
    extern __shared__ float sm[];
    float* sAh = sm;                 // [128][36]
    float* sAl = sm + 128*KP;
    float* sBh = sm + 2*128*KP;
    float* sBl = sm + 3*128*KP;

    int tid = threadIdx.x;
    int lane = tid & 31, warp = tid >> 5;
    int warpM = warp >> 1;           // 0..3 -> 32-row slab
    int warpN = warp & 1;            // 0..1 -> 64-col slab
    int gid = lane >> 2, tig = lane & 3;

    const float* Ab = A + (size_t)blockIdx.y * 128 * DD;
    const float* Bb = B + (size_t)blockIdx.x * 128 * DD;

    float acc[2][8][4];
#pragma unroll
    for (int mt = 0; mt < 2; mt++)
#pragma unroll
        for (int nt = 0; nt < 8; nt++)
#pragma unroll
            for (int i = 0; i < 4; i++) acc[mt][nt][i] = 0.f;

    int r0 = tid >> 3;   // staging row (u adds 32)
    int q0 = tid & 7;    // float4 index within 32-wide k-chunk

    float4 pA[4], pB[4];
#pragma unroll
    for (int u = 0; u < 4; u++){
        pA[u] = *(const float4*)(Ab + (size_t)(r0 + u*32) * DD + q0*4);
        pB[u] = *(const float4*)(Bb + (size_t)(r0 + u*32) * DD + q0*4);
    }

    for (int kt = 0; kt < DD/32; kt++){
        if (kt > 0) __syncthreads();   // all warps done with previous tile
        // split + stage
#pragma unroll
        for (int u = 0; u < 4; u++){
            int r = r0 + u*32;
            float4 h, l;
            tf32_split(pA[u].x, h.x, l.x); tf32_split(pA[u].y, h.y, l.y);
            tf32_split(pA[u].z, h.z, l.z); tf32_split(pA[u].w, h.w, l.w);
            *(float4*)(sAh + r*KP + q0*4) = h;
            *(float4*)(sAl + r*KP + q0*4) = l;
            tf32_split(pB[u].x, h.x, l.x); tf32_split(pB[u].y, h.y, l.y);
            tf32_split(pB[u].z, h.z, l.z); tf32_split(pB[u].w, h.w, l.w);
            *(float4*)(sBh + r*KP + q0*4) = h;
            *(float4*)(sBl + r*KP + q0*4) = l;
        }
        __syncthreads();
        // prefetch next tile
        if (kt + 1 < DD/32){
            int kc = (kt + 1) * 32;
#pragma unroll
            for (int u = 0; u < 4; u++){
                pA[u] = *(const float4*)(Ab + (size_t)(r0 + u*32) * DD + kc + q0*4);
                pB[u] = *(const float4*)(Bb + (size_t)(r0 + u*32) * DD + kc + q0*4);
            }
        }
        // compute 4 k8-steps
#pragma unroll
        for (int ks = 0; ks < 4; ks++){
            int k0 = ks * 8;
            unsigned ah[2][4], al[2][4];
#pragma unroll
            for (int mt = 0; mt < 2; mt++){
                int ar = warpM*32 + mt*16 + gid;
                const float* ph = sAh + ar*KP + k0 + tig;
                const float* pl = sAl + ar*KP + k0 + tig;
                ah[mt][0] = __float_as_uint(ph[0]);
                ah[mt][1] = __float_as_uint(ph[8*KP]);
                ah[mt][2] = __float_as_uint(ph[4]);
                ah[mt][3] = __float_as_uint(ph[8*KP + 4]);
                al[mt][0] = __float_as_uint(pl[0]);
                al[mt][1] = __float_as_uint(pl[8*KP]);
                al[mt][2] = __float_as_uint(pl[4]);
                al[mt][3] = __float_as_uint(pl[8*KP + 4]);
            }
            unsigned bh[8][2], bl[8][2];
#pragma unroll
            for (int nt = 0; nt < 8; nt++){
                int br = warpN*64 + nt*8 + gid;
                const float* ph = sBh + br*KP + k0 + tig;
                const float* pl = sBl + br*KP + k0 + tig;
                bh[nt][0] = __float_as_uint(ph[0]);
                bh[nt][1] = __float_as_uint(ph[4]);
                bl[nt][0] = __float_as_uint(pl[0]);
                bl[nt][1] = __float_as_uint(pl[4]);
            }
#pragma unroll
            for (int mt = 0; mt < 2; mt++)
#pragma unroll
                for (int nt = 0; nt < 8; nt++){
                    MMA_TF32(acc[mt][nt], ah[mt][0],ah[mt][1],ah[mt][2],ah[mt][3],
                             bh[nt][0], bh[nt][1]);
                    MMA_TF32(acc[mt][nt], ah[mt][0],ah[mt][1],ah[mt][2],ah[mt][3],
                             bl[nt][0], bl[nt][1]);
                    MMA_TF32(acc[mt][nt], al[mt][0],al[mt][1],al[mt][2],al[mt][3],
                             bh[nt][0], bh[nt][1]);
                }
        }
    }

    // write back
    int mBase = blockIdx.y*128 + warpM*32;
    int nBase = blockIdx.x*128 + warpN*64;
#pragma unroll
    for (int mt = 0; mt < 2; mt++)
#pragma unroll
        for (int nt = 0; nt < 8; nt++){
            int m0 = mBase + mt*16 + gid;
            int n0 = nBase + nt*8 + tig*2;
            float2 v0 = {acc[mt][nt][0], acc[mt][nt][1]};
            float2 v1 = {acc[mt][nt][2], acc[mt][nt][3]};
            *(float2*)(Cg + (size_t)m0 * NN + n0) = v0;
            *(float2*)(Cg + (size_t)(m0+8) * NN + n0) = v1;
        }
}

// ---------------- epilogue: per (n,t) pair attention + focal + cosine ----------------
__global__ void epilogue_kernel(const int* __restrict__ tlen, float* __restrict__ out){
    __shared__ float sS[RR*65];    // leaky(S) tile  [48][65]
    __shared__ float sCt[LW*49];   // C tile transposed [64][49]: sCt[l*49+r]
    __shared__ float sGH[LW*65];   // G tile [64][65], later H tile [48][49]
    __shared__ float colnorm[LW];
    __shared__ float rownorm[RR];
    __shared__ float wacc[8];

    int n = blockIdx.y, t = blockIdx.x;
    int tid = threadIdx.x, warp = tid >> 5, lane = tid & 31;
    int len = tlen[t];
    float lenf = (float)len;

    for (int idx = tid; idx < RR*16; idx += 256){
        int r = idx >> 4, q = idx & 15;
        float4 v = *(const float4*)(g_S + (size_t)(n*RR + r) * NN + t*LW + q*4);
        float* d = &sS[r*65 + q*4];
        d[0] = v.x >= 0.f ? v.x : 0.1f*v.x;
        d[1] = v.y >= 0.f ? v.y : 0.1f*v.y;
        d[2] = v.z >= 0.f ? v.z : 0.1f*v.z;
        d[3] = v.w >= 0.f ? v.w : 0.1f*v.w;
    }
    for (int idx = tid; idx < RR*16; idx += 256){
        int r = idx >> 4, q = idx & 15;
        float4 v = *(const float4*)(g_C + (size_t)(n*RR + r) * NN + t*LW + q*4);
        sCt[(q*4+0)*49 + r] = v.x; sCt[(q*4+1)*49 + r] = v.y;
        sCt[(q*4+2)*49 + r] = v.z; sCt[(q*4+3)*49 + r] = v.w;
    }
    for (int idx = tid; idx < LW*16; idx += 256){
        int l = idx >> 4, q = idx & 15;
        float4 v = *(const float4*)(g_G + (size_t)t*LW*LW + l*LW + q*4);
        float* d = &sGH[l*65 + q*4];
        d[0] = v.x; d[1] = v.y; d[2] = v.z; d[3] = v.w;
    }
    __syncthreads();

    if (tid < LW){
        float s = 0.f;
        for (int r = 0; r < RR; r++){ float v = sS[r*65 + tid]; s += v*v; }
        colnorm[tid] = sqrtf(s) + EPSV;
    } else if (tid < LW + RR){
        int r = tid - LW; float s = 0.f;
        for (int l = 0; l < LW; l++){ float v = sS[r*65 + l]; s += v*v; }
        rownorm[r] = sqrtf(s) + EPSV;
    }
    __syncthreads();

    // ---- i2t ----
    float accI = 0.f;
    for (int r = warp; r < RR; r += 8){
        int l0 = lane, l1 = lane + 32;
        bool m0 = l0 < len, m1 = l1 < len;
        float x0 = m0 ? sS[r*65 + l0] / colnorm[l0] * LAM : -1e30f;
        float x1 = m1 ? sS[r*65 + l1] / colnorm[l1] * LAM : -1e30f;
        float mx = wmax(fmaxf(x0, x1));
        float e0 = m0 ? expf(x0 - mx) : 0.f;
        float e1 = m1 ? expf(x1 - mx) : 0.f;
        float sE = wsum(e0 + e1);
        float a0 = e0 / sE, a1 = e1 / sE;
        float sA = wsum(a0 + a1);
        float ta0 = (a0 * lenf - sA > 0.f) ? a0 : 0.f;
        float ta1 = (a1 * lenf - sA > 0.f) ? a1 : 0.f;
        float sT = wsum(ta0 + ta1);
        float dn = sT > 0.f ? sT : 1.f;
        float f0 = ta0 / dn, f1 = ta1 / dn;
        float num = wsum(f0 * sCt[l0*49 + r] + f1 * sCt[l1*49 + r]);
        float qd = 0.f;
        for (int lp = 0; lp < LW; lp++){
            float alp = (lp < 32) ? __shfl_sync(0xffffffffu, f0, lp)
                                  : __shfl_sync(0xffffffffu, f1, lp - 32);
            qd += alp * (f0 * sGH[l0*65 + lp] + f1 * sGH[l1*65 + lp]);
        }
        qd = wsum(qd);
        float wn = sqrtf(fmaxf(qd, 0.f));
        float inv = 1.f / (wn + EPSV);
        float xw = num * inv, whn = wn * inv;
        float den = fmaxf(g_niv[n*RR + r] * whn, EPSV);
        accI += xw / den;
    }
    if (lane == 0) wacc[warp] = accI;
    __syncthreads();
    if (tid == 0){
        float s = 0.f;
        for (int i = 0; i < 8; i++) s += wacc[i];
        out[n*NT + t] = s / (float)RR;
    }
    __syncthreads();

    for (int idx = tid; idx < RR*RR; idx += 256){
        int r = idx / RR, c = idx - r*RR;
        sGH[r*49 + c] = g_H[(size_t)n*RR*RR + idx];
    }
    __syncthreads();

    // ---- t2i ----
    float accT = 0.f;
    for (int l = warp; l < LW; l += 8){
        int r0 = lane;
        bool h1 = lane < 16;
        int r1 = lane + 32;
        float y0 = sS[r0*65 + l] / rownorm[r0] * LAM;
        float y1 = h1 ? sS[r1*65 + l] / rownorm[r1] * LAM : -1e30f;
        float mx = wmax(fmaxf(y0, y1));
        float e0 = expf(y0 - mx);
        float e1 = h1 ? expf(y1 - mx) : 0.f;
        float sE = wsum(e0 + e1);
        float a0 = e0 / sE, a1 = e1 / sE;
        float sA = wsum(a0 + a1);
        float ta0 = (a0 * (float)RR - sA > 0.f) ? a0 : 0.f;
        float ta1 = (a1 * (float)RR - sA > 0.f) ? a1 : 0.f;
        float sT = wsum(ta0 + ta1);
        float dn = sT > 0.f ? sT : 1.f;
        float f0 = ta0 / dn, f1 = ta1 / dn;
        float num = f0 * sCt[l*49 + r0] + (h1 ? f1 * sCt[l*49 + r1] : 0.f);
        num = wsum(num);
        float qd = 0.f;
        for (int rp = 0; rp < RR; rp++){
            float arp = (rp < 32) ? __shfl_sync(0xffffffffu, f0, rp)
                                  : __shfl_sync(0xffffffffu, f1, rp - 32);
            float term = f0 * sGH[r0*49 + rp];
            if (h1) term += f1 * sGH[r1*49 + rp];
            qd += arp * term;
        }
        qd = wsum(qd);
        float wn = sqrtf(fmaxf(qd, 0.f));
        float inv = 1.f / (wn + EPSV);
        float xw = num * inv, whn = wn * inv;
        float den = fmaxf(g_ntv[t*LW + l] * whn, EPSV);
        float c2 = xw / den;
        if (l < len) accT += c2;
    }
    if (lane == 0) wacc[warp] = accT;
    __syncthreads();
    if (tid == 0){
        float s = 0.f;
        for (int i = 0; i < 8; i++) s += wacc[i];
        out[NI*NT + n*NT + t] = s / lenf;
    }
}

// ---------------- launch ----------------
extern "C" void kernel_launch(void* const* d_in, const int* in_sizes, int n_in,
                              void* d_out, int out_size){
    (void)in_sizes; (void)n_in; (void)out_size;
    const float* img_q = (const float*)d_in[0];
    const float* img_v = (const float*)d_in[1];
    const float* txt_k = (const float*)d_in[2];
    const float* txt_v = (const float*)d_in[3];
    const int*   tlen  = (const int*)d_in[4];
    float* out = (float*)d_out;

    void *pqn, *ptkn, *pS, *pC, *pG, *pH;
    cudaGetSymbolAddress(&pqn, g_qn);
    cudaGetSymbolAddress(&ptkn, g_tkn);
    cudaGetSymbolAddress(&pS, g_S);
    cudaGetSymbolAddress(&pC, g_C);
    cudaGetSymbolAddress(&pG, g_G);
    cudaGetSymbolAddress(&pH, g_H);

    const int smemGemm = 4 * 128 * KP * (int)sizeof(float);  // 73728 B
    cudaFuncSetAttribute(sgemm_tf32x3, cudaFuncAttributeMaxDynamicSharedMemorySize, smemGemm);

    prep_img_kernel<<<MM, 256>>>(img_q, img_v);
    prep_txt_kernel<<<NN, 256>>>(txt_k, txt_v, tlen);
    gram_kernel<RR><<<NI, 256>>>(img_v, (float*)pH);
    gram_kernel<LW><<<NT, 256>>>(txt_v, (float*)pG);

    dim3 gg(NN/128, MM/128);   // 64 x 48
    sgemm_tf32x3<<<gg, 256, smemGemm>>>((const float*)pqn, (const float*)ptkn, (float*)pS);
    sgemm_tf32x3<<<gg, 256, smemGemm>>>(img_v, txt_v, (float*)pC);

    dim3 ge(NT, NI);           // x = t, y = n
    epilogue_kernel<<<ge, 256>>>(tlen, out);
}

// round 7
// speedup vs baseline: 1.7462x; 1.3727x over previous
#include <cuda_runtime.h>
#include <cuda_fp16.h>
#include <math.h>
#include <stdint.h>

#define NI 128
#define NT 128
#define RR 48
#define LW 64
#define DD 1024
#define MM (NI*RR)   /* 6144 */
#define NN (NT*LW)   /* 8192 */
#define EPSV 1e-8f
#define LAM 20.0f

// ---------------- scratch (static device globals; no allocation) ----------------
__device__ float g_qn[MM*DD];                 // 25 MB  normalized img_q
__device__ float g_tkn[NN*DD];                // 34 MB  masked-normalized txt_k
__device__ float g_S[50331648];               // 201 MB S = qn . tkn^T   [6144 x 8192]
__device__ float g_C[50331648];               // 201 MB C = img_v . txt_v^T
__device__ float g_G[NT*LW*LW];               // 2 MB   per-text Gram of txt_v
__device__ float g_H[NI*RR*RR];               // 1.2 MB per-image Gram of img_v
__device__ float g_niv[MM];                   // |img_v[n,r]|
__device__ float g_ntv[NN];                   // |txt_v[t,l]|

// ---------------- warp helpers ----------------
__device__ __forceinline__ float wsum(float v){
#pragma unroll
    for (int o = 16; o; o >>= 1) v += __shfl_xor_sync(0xffffffffu, v, o);
    return v;
}
__device__ __forceinline__ float wmax(float v){
#pragma unroll
    for (int o = 16; o; o >>= 1) v = fmaxf(v, __shfl_xor_sync(0xffffffffu, v, o));
    return v;
}

// ---------------- prep: normalize img_q rows, norms of img_v rows ----------------
__global__ void prep_img_kernel(const float* __restrict__ q, const float* __restrict__ v){
    int row = blockIdx.x, tid = threadIdx.x;
    const float4* q4 = (const float4*)(q + (size_t)row * DD);
    const float4* v4 = (const float4*)(v + (size_t)row * DD);
    float4 a = q4[tid], b = v4[tid];
    float sq = a.x*a.x + a.y*a.y + a.z*a.z + a.w*a.w;
    float sv = b.x*b.x + b.y*b.y + b.z*b.z + b.w*b.w;
    __shared__ float s1[8], s2[8];
    sq = wsum(sq); sv = wsum(sv);
    int w = tid >> 5, ln = tid & 31;
    if (ln == 0){ s1[w] = sq; s2[w] = sv; }
    __syncthreads();
    if (tid == 0){
        float t1 = 0.f, t2 = 0.f;
        for (int i = 0; i < 8; i++){ t1 += s1[i]; t2 += s2[i]; }
        s1[0] = t1;
        g_niv[row] = sqrtf(t2);
    }
    __syncthreads();
    float inv = 1.0f / (sqrtf(s1[0]) + EPSV);
    float4 o; o.x = a.x*inv; o.y = a.y*inv; o.z = a.z*inv; o.w = a.w*inv;
    ((float4*)(g_qn + (size_t)row * DD))[tid] = o;
}

// ---------------- prep: masked-normalize txt_k rows, norms of txt_v rows ----------------
__global__ void prep_txt_kernel(const float* __restrict__ k, const float* __restrict__ v,
                                const int* __restrict__ tlen){
    int row = blockIdx.x, tid = threadIdx.x;
    int t = row >> 6, l = row & 63;
    int len = tlen[t];
    const float4* k4 = (const float4*)(k + (size_t)row * DD);
    const float4* v4 = (const float4*)(v + (size_t)row * DD);
    float4 a = k4[tid], b = v4[tid];
    float sk = a.x*a.x + a.y*a.y + a.z*a.z + a.w*a.w;
    float sv = b.x*b.x + b.y*b.y + b.z*b.z + b.w*b.w;
    __shared__ float s1[8], s2[8];
    sk = wsum(sk); sv = wsum(sv);
    int w = tid >> 5, ln = tid & 31;
    if (ln == 0){ s1[w] = sk; s2[w] = sv; }
    __syncthreads();
    if (tid == 0){
        float t1 = 0.f, t2 = 0.f;
        for (int i = 0; i < 8; i++){ t1 += s1[i]; t2 += s2[i]; }
        s1[0] = t1;
        g_ntv[row] = sqrtf(t2);
    }
    __syncthreads();
    float inv = (l < len) ? (1.0f / (sqrtf(s1[0]) + EPSV)) : 0.0f;
    float4 o; o.x = a.x*inv; o.y = a.y*inv; o.z = a.z*inv; o.w = a.w*inv;
    ((float4*)(g_tkn + (size_t)row * DD))[tid] = o;
}

// ---------------- per-batch Gram: out[b] = X[b] X[b]^T, X[b] is [Rn,1024] ----------------
template<int Rn>
__global__ void gram_kernel(const float* __restrict__ X, float* __restrict__ out){
    __shared__ float sX[64][65];
    int b = blockIdx.x, tid = threadIdx.x;
    int tx = tid & 15, ty = tid >> 4;
    const float* Xb = X + (size_t)b * Rn * DD;
    int i0 = ty * 4, j0 = tx * 4;
    bool act = (i0 < Rn) && (j0 < Rn);
    float acc[4][4];
#pragma unroll
    for (int i = 0; i < 4; i++)
#pragma unroll
        for (int j = 0; j < 4; j++) acc[i][j] = 0.f;
    const int nld = Rn * 16;
    for (int kc = 0; kc < DD; kc += 64){
        for (int idx = tid; idx < nld; idx += 256){
            int r = idx >> 4, kq = idx & 15;
            float4 val = *(const float4*)(Xb + (size_t)r * DD + kc + kq * 4);
            sX[r][kq*4+0] = val.x; sX[r][kq*4+1] = val.y;
            sX[r][kq*4+2] = val.z; sX[r][kq*4+3] = val.w;
        }
        __syncthreads();
        if (act){
#pragma unroll 8
            for (int k = 0; k < 64; k++){
                float ai0 = sX[i0+0][k], ai1 = sX[i0+1][k], ai2 = sX[i0+2][k], ai3 = sX[i0+3][k];
                float bj0 = sX[j0+0][k], bj1 = sX[j0+1][k], bj2 = sX[j0+2][k], bj3 = sX[j0+3][k];
                acc[0][0] += ai0*bj0; acc[0][1] += ai0*bj1; acc[0][2] += ai0*bj2; acc[0][3] += ai0*bj3;
                acc[1][0] += ai1*bj0; acc[1][1] += ai1*bj1; acc[1][2] += ai1*bj2; acc[1][3] += ai1*bj3;
                acc[2][0] += ai2*bj0; acc[2][1] += ai2*bj1; acc[2][2] += ai2*bj2; acc[2][3] += ai2*bj3;
                acc[3][0] += ai3*bj0; acc[3][1] += ai3*bj1; acc[3][2] += ai3*bj2; acc[3][3] += ai3*bj3;
            }
        }
        __syncthreads();
    }
    if (act){
        float* ob = out + (size_t)b * Rn * Rn;
#pragma unroll
        for (int a = 0; a < 4; a++)
#pragma unroll
            for (int c = 0; c < 4; c++)
                ob[(i0+a)*Rn + j0 + c] = acc[a][c];
    }
}

// ---------------- fp16x3 tensor-core GEMM (mma.sync m16n8k16) ----------------
// Cg[M,NN] = A[M,1024] * B[NN,1024]^T.  CTA tile 128x128, K-chunk 32,
// 8 warps each computing 32x64.  hi/lo fp16 split: residual ~2^-22.

#define KP2 40   /* padded k-stride in halves (80 B): conflict-free frags, 16B aligned */

#define MMA_F16(d, a0,a1,a2,a3, b0,b1) \
    asm volatile("mma.sync.aligned.m16n8k16.row.col.f32.f16.f16.f32 " \
        "{%0,%1,%2,%3}, {%4,%5,%6,%7}, {%8,%9}, {%0,%1,%2,%3};" \
        : "+f"(d[0]), "+f"(d[1]), "+f"(d[2]), "+f"(d[3]) \
        : "r"(a0), "r"(a1), "r"(a2), "r"(a3), "r"(b0), "r"(b1))

__device__ __forceinline__ uint32_t h2u(__half2 h){ return *reinterpret_cast<uint32_t*>(&h); }

// split float2 -> (hi half2, lo half2)
__device__ __forceinline__ void f2_split(float x, float y, uint32_t& hi, uint32_t& lo){
    __half2 h = __floats2half2_rn(x, y);
    float2 f = __half22float2(h);
    __half2 l = __floats2half2_rn(x - f.x, y - f.y);
    hi = h2u(h); lo = h2u(l);
}

__global__ __launch_bounds__(256, 1)
void sgemm_f16x3(const float* __restrict__ A, const float* __restrict__ B,
                 float* __restrict__ Cg){
    extern __shared__ __half sm[];
    __half* sAh = sm;                 // [128][KP2]
    __half* sAl = sm + 128*KP2;
    __half* sBh = sm + 2*128*KP2;
    __half* sBl = sm + 3*128*KP2;

    int tid = threadIdx.x;
    int lane = tid & 31, warp = tid >> 5;
    int warpM = warp >> 1;           // 0..3 -> 32-row slab
    int warpN = warp & 1;            // 0..1 -> 64-col slab
    int gid = lane >> 2, tig = lane & 3;

    const float* Ab = A + (size_t)blockIdx.y * 128 * DD;
    const float* Bb = B + (size_t)blockIdx.x * 128 * DD;

    float acc[2][8][4];
#pragma unroll
    for (int mt = 0; mt < 2; mt++)
#pragma unroll
        for (int nt = 0; nt < 8; nt++)
#pragma unroll
            for (int i = 0; i < 4; i++) acc[mt][nt][i] = 0.f;

    int r0 = tid >> 3;   // staging row (u adds 32)
    int q0 = tid & 7;    // float4 index within 32-wide k-chunk

    float4 pA[4], pB[4];
#pragma unroll
    for (int u = 0; u < 4; u++){
        pA[u] = *(const float4*)(Ab + (size_t)(r0 + u*32) * DD + q0*4);
        pB[u] = *(const float4*)(Bb + (size_t)(r0 + u*32) * DD + q0*4);
    }

    for (int kt = 0; kt < DD/32; kt++){
        if (kt > 0) __syncthreads();   // all warps done with previous tile
        // split + stage (each float4 -> uint2 hi + uint2 lo)
#pragma unroll
        for (int u = 0; u < 4; u++){
            int r = r0 + u*32;
            uint32_t h0, h1, l0, l1;
            f2_split(pA[u].x, pA[u].y, h0, l0);
            f2_split(pA[u].z, pA[u].w, h1, l1);
            *(uint2*)(sAh + r*KP2 + q0*4) = make_uint2(h0, h1);
            *(uint2*)(sAl + r*KP2 + q0*4) = make_uint2(l0, l1);
            f2_split(pB[u].x, pB[u].y, h0, l0);
            f2_split(pB[u].z, pB[u].w, h1, l1);
            *(uint2*)(sBh + r*KP2 + q0*4) = make_uint2(h0, h1);
            *(uint2*)(sBl + r*KP2 + q0*4) = make_uint2(l0, l1);
        }
        __syncthreads();
        // prefetch next tile
        if (kt + 1 < DD/32){
            int kc = (kt + 1) * 32;
#pragma unroll
            for (int u = 0; u < 4; u++){
                pA[u] = *(const float4*)(Ab + (size_t)(r0 + u*32) * DD + kc + q0*4);
                pB[u] = *(const float4*)(Bb + (size_t)(r0 + u*32) * DD + kc + q0*4);
            }
        }
        // compute: 2 k16-steps per chunk
#pragma unroll
        for (int ks = 0; ks < 2; ks++){
            int k0 = ks * 16;
            uint32_t ah[2][4], al[2][4];
#pragma unroll
            for (int mt = 0; mt < 2; mt++){
                int ar = warpM*32 + mt*16 + gid;
                const __half* ph = sAh + ar*KP2 + k0 + 2*tig;
                const __half* pl = sAl + ar*KP2 + k0 + 2*tig;
                ah[mt][0] = *(const uint32_t*)(ph);
                ah[mt][1] = *(const uint32_t*)(ph + 8*KP2);
                ah[mt][2] = *(const uint32_t*)(ph + 8);
                ah[mt][3] = *(const uint32_t*)(ph + 8*KP2 + 8);
                al[mt][0] = *(const uint32_t*)(pl);
                al[mt][1] = *(const uint32_t*)(pl + 8*KP2);
                al[mt][2] = *(const uint32_t*)(pl + 8);
                al[mt][3] = *(const uint32_t*)(pl + 8*KP2 + 8);
            }
            uint32_t bh[8][2], bl[8][2];
#pragma unroll
            for (int nt = 0; nt < 8; nt++){
                int br = warpN*64 + nt*8 + gid;
                const __half* ph = sBh + br*KP2 + k0 + 2*tig;
                const __half* pl = sBl + br*KP2 + k0 + 2*tig;
                bh[nt][0] = *(const uint32_t*)(ph);
                bh[nt][1] = *(const uint32_t*)(ph + 8);
                bl[nt][0] = *(const uint32_t*)(pl);
                bl[nt][1] = *(const uint32_t*)(pl + 8);
            }
#pragma unroll
            for (int mt = 0; mt < 2; mt++)
#pragma unroll
                for (int nt = 0; nt < 8; nt++){
                    MMA_F16(acc[mt][nt], ah[mt][0],ah[mt][1],ah[mt][2],ah[mt][3],
                            bh[nt][0], bh[nt][1]);
                    MMA_F16(acc[mt][nt], ah[mt][0],ah[mt][1],ah[mt][2],ah[mt][3],
                            bl[nt][0], bl[nt][1]);
                    MMA_F16(acc[mt][nt], al[mt][0],al[mt][1],al[mt][2],al[mt][3],
                            bh[nt][0], bh[nt][1]);
                }
        }
    }

    // write back
    int mBase = blockIdx.y*128 + warpM*32;
    int nBase = blockIdx.x*128 + warpN*64;
#pragma unroll
    for (int mt = 0; mt < 2; mt++)
#pragma unroll
        for (int nt = 0; nt < 8; nt++){
            int m0 = mBase + mt*16 + gid;
            int n0 = nBase + nt*8 + tig*2;
            float2 v0 = {acc[mt][nt][0], acc[mt][nt][1]};
            float2 v1 = {acc[mt][nt][2], acc[mt][nt][3]};
            *(float2*)(Cg + (size_t)m0 * NN + n0) = v0;
            *(float2*)(Cg + (size_t)(m0+8) * NN + n0) = v1;
        }
}

// ---------------- epilogue: per (n,t) pair attention + focal + cosine ----------------
__global__ void epilogue_kernel(const int* __restrict__ tlen, float* __restrict__ out){
    __shared__ float sS[RR*65];
    __shared__ float sCt[LW*49];
    __shared__ float sGH[LW*65];
    __shared__ float colnorm[LW];
    __shared__ float rownorm[RR];
    __shared__ float wacc[8];

    int n = blockIdx.y, t = blockIdx.x;
    int tid = threadIdx.x, warp = tid >> 5, lane = tid & 31;
    int len = tlen[t];
    float lenf = (float)len;

    for (int idx = tid; idx < RR*16; idx += 256){
        int r = idx >> 4, q = idx & 15;
        float4 v = *(const float4*)(g_S + (size_t)(n*RR + r) * NN + t*LW + q*4);
        float* d = &sS[r*65 + q*4];
        d[0] = v.x >= 0.f ? v.x : 0.1f*v.x;
        d[1] = v.y >= 0.f ? v.y : 0.1f*v.y;
        d[2] = v.z >= 0.f ? v.z : 0.1f*v.z;
        d[3] = v.w >= 0.f ? v.w : 0.1f*v.w;
    }
    for (int idx = tid; idx < RR*16; idx += 256){
        int r = idx >> 4, q = idx & 15;
        float4 v = *(const float4*)(g_C + (size_t)(n*RR + r) * NN + t*LW + q*4);
        sCt[(q*4+0)*49 + r] = v.x; sCt[(q*4+1)*49 + r] = v.y;
        sCt[(q*4+2)*49 + r] = v.z; sCt[(q*4+3)*49 + r] = v.w;
    }
    for (int idx = tid; idx < LW*16; idx += 256){
        int l = idx >> 4, q = idx & 15;
        float4 v = *(const float4*)(g_G + (size_t)t*LW*LW + l*LW + q*4);
        float* d = &sGH[l*65 + q*4];
        d[0] = v.x; d[1] = v.y; d[2] = v.z; d[3] = v.w;
    }
    __syncthreads();

    if (tid < LW){
        float s = 0.f;
        for (int r = 0; r < RR; r++){ float v = sS[r*65 + tid]; s += v*v; }
        colnorm[tid] = sqrtf(s) + EPSV;
    } else if (tid < LW + RR){
        int r = tid - LW; float s = 0.f;
        for (int l = 0; l < LW; l++){ float v = sS[r*65 + l]; s += v*v; }
        rownorm[r] = sqrtf(s) + EPSV;
    }
    __syncthreads();

    // ---- i2t ----
    float accI = 0.f;
    for (int r = warp; r < RR; r += 8){
        int l0 = lane, l1 = lane + 32;
        bool m0 = l0 < len, m1 = l1 < len;
        float x0 = m0 ? sS[r*65 + l0] / colnorm[l0] * LAM : -1e30f;
        float x1 = m1 ? sS[r*65 + l1] / colnorm[l1] * LAM : -1e30f;
        float mx = wmax(fmaxf(x0, x1));
        float e0 = m0 ? expf(x0 - mx) : 0.f;
        float e1 = m1 ? expf(x1 - mx) : 0.f;
        float sE = wsum(e0 + e1);
        float a0 = e0 / sE, a1 = e1 / sE;
        float sA = wsum(a0 + a1);
        float ta0 = (a0 * lenf - sA > 0.f) ? a0 : 0.f;
        float ta1 = (a1 * lenf - sA > 0.f) ? a1 : 0.f;
        float sT = wsum(ta0 + ta1);
        float dn = sT > 0.f ? sT : 1.f;
        float f0 = ta0 / dn, f1 = ta1 / dn;
        float num = wsum(f0 * sCt[l0*49 + r] + f1 * sCt[l1*49 + r]);
        float qd = 0.f;
        for (int lp = 0; lp < LW; lp++){
            float alp = (lp < 32) ? __shfl_sync(0xffffffffu, f0, lp)
                                  : __shfl_sync(0xffffffffu, f1, lp - 32);
            qd += alp * (f0 * sGH[l0*65 + lp] + f1 * sGH[l1*65 + lp]);
        }
        qd = wsum(qd);
        float wn = sqrtf(fmaxf(qd, 0.f));
        float inv = 1.f / (wn + EPSV);
        float xw = num * inv, whn = wn * inv;
        float den = fmaxf(g_niv[n*RR + r] * whn, EPSV);
        accI += xw / den;
    }
    if (lane == 0) wacc[warp] = accI;
    __syncthreads();
    if (tid == 0){
        float s = 0.f;
        for (int i = 0; i < 8; i++) s += wacc[i];
        out[n*NT + t] = s / (float)RR;
    }
    __syncthreads();

    for (int idx = tid; idx < RR*RR; idx += 256){
        int r = idx / RR, c = idx - r*RR;
        sGH[r*49 + c] = g_H[(size_t)n*RR*RR + idx];
    }
    __syncthreads();

    // ---- t2i ----
    float accT = 0.f;
    for (int l = warp; l < LW; l += 8){
        int r0 = lane;
        bool h1 = lane < 16;
        int r1 = lane + 32;
        float y0 = sS[r0*65 + l] / rownorm[r0] * LAM;
        float y1 = h1 ? sS[r1*65 + l] / rownorm[r1] * LAM : -1e30f;
        float mx = wmax(fmaxf(y0, y1));
        float e0 = expf(y0 - mx);
        float e1 = h1 ? expf(y1 - mx) : 0.f;
        float sE = wsum(e0 + e1);
        float a0 = e0 / sE, a1 = e1 / sE;
        float sA = wsum(a0 + a1);
        float ta0 = (a0 * (float)RR - sA > 0.f) ? a0 : 0.f;
        float ta1 = (a1 * (float)RR - sA > 0.f) ? a1 : 0.f;
        float sT = wsum(ta0 + ta1);
        float dn = sT > 0.f ? sT : 1.f;
        float f0 = ta0 / dn, f1 = ta1 / dn;
        float num = f0 * sCt[l*49 + r0] + (h1 ? f1 * sCt[l*49 + r1] : 0.f);
        num = wsum(num);
        float qd = 0.f;
        for (int rp = 0; rp < RR; rp++){
            float arp = (rp < 32) ? __shfl_sync(0xffffffffu, f0, rp)
                                  : __shfl_sync(0xffffffffu, f1, rp - 32);
            float term = f0 * sGH[r0*49 + rp];
            if (h1) term += f1 * sGH[r1*49 + rp];
            qd += arp * term;
        }
        qd = wsum(qd);
        float wn = sqrtf(fmaxf(qd, 0.f));
        float inv = 1.f / (wn + EPSV);
        float xw = num * inv, whn = wn * inv;
        float den = fmaxf(g_ntv[t*LW + l] * whn, EPSV);
        float c2 = xw / den;
        if (l < len) accT += c2;
    }
    if (lane == 0) wacc[warp] = accT;
    __syncthreads();
    if (tid == 0){
        float s = 0.f;
        for (int i = 0; i < 8; i++) s += wacc[i];
        out[NI*NT + n*NT + t] = s / lenf;
    }
}

// ---------------- launch ----------------
extern "C" void kernel_launch(void* const* d_in, const int* in_sizes, int n_in,
                              void* d_out, int out_size){
    (void)in_sizes; (void)n_in; (void)out_size;
    const float* img_q = (const float*)d_in[0];
    const float* img_v = (const float*)d_in[1];
    const float* txt_k = (const float*)d_in[2];
    const float* txt_v = (const float*)d_in[3];
    const int*   tlen  = (const int*)d_in[4];
    float* out = (float*)d_out;

    void *pqn, *ptkn, *pS, *pC, *pG, *pH;
    cudaGetSymbolAddress(&pqn, g_qn);
    cudaGetSymbolAddress(&ptkn, g_tkn);
    cudaGetSymbolAddress(&pS, g_S);
    cudaGetSymbolAddress(&pC, g_C);
    cudaGetSymbolAddress(&pG, g_G);
    cudaGetSymbolAddress(&pH, g_H);

    const int smemGemm = 4 * 128 * KP2 * (int)sizeof(__half);  // 40960 B
    cudaFuncSetAttribute(sgemm_f16x3, cudaFuncAttributeMaxDynamicSharedMemorySize, smemGemm);

    prep_img_kernel<<<MM, 256>>>(img_q, img_v);
    prep_txt_kernel<<<NN, 256>>>(txt_k, txt_v, tlen);
    gram_kernel<RR><<<NI, 256>>>(img_v, (float*)pH);
    gram_kernel<LW><<<NT, 256>>>(txt_v, (float*)pG);

    dim3 gg(NN/128, MM/128);   // 64 x 48
    sgemm_f16x3<<<gg, 256, smemGemm>>>((const float*)pqn, (const float*)ptkn, (float*)pS);
    sgemm_f16x3<<<gg, 256, smemGemm>>>(img_v, txt_v, (float*)pC);

    dim3 ge(NT, NI);           // x = t, y = n
    epilogue_kernel<<<ge, 256>>>(tlen, out);
}